// round 10
// baseline (speedup 1.0000x reference)
#include <cuda_runtime.h>
#include <cuda_bf16.h>
#include <cstdint>

// TemporalCooccurrenceMatrix — round 10: R9 compute + PDL overlap.
// prep triggers programmatic launch completion; cooc launches early (PSS attr),
// does its prep-independent prologue, then cudaGridDependencySynchronize()
// before touching g_e2/g_pnp. Erases the inter-kernel gap and hides prep.
//
// C[b,w1,w2] = sum_{l1,l2} [node==][mask&mask] * e^{-(l1-l2)^2/4}*e^{-|t1-t2|/5}
// out = tanh(min(C,10)); symmetric -> rows r and 127-r paired per CTA (512 CTAs).
// e^{-|a-b|/5} = min(e^{a/5}e^{-b/5}, e^{-a/5}e^{b/5}); prep precomputes
// (e^{+t/5},e^{-t/5}) and padded node bytes (32 = masked/pad sentinel).

#define TOT   20480            // 8*128*20
#define PTOT  32768            // 8*128*32 padded node bytes (16 per half)
#define BPREP 256
#define BDIM  288              // 2 threads x 129 targets = 258 active

__device__ __align__(16) float2        g_e2[TOT];   // (e^{+t/5}, e^{-t/5})
__device__ __align__(16) unsigned char g_pnp[PTOT]; // node 0..31, 32 = invalid

__global__ __launch_bounds__(BPREP)
void prep_kernel(const void* __restrict__ nodes_raw,
                 const void* __restrict__ masks_raw,
                 const float* __restrict__ times)
{
    __shared__ int s_n64, s_m32;
    if (threadIdx.x < 32) {
        const unsigned int*  nw = (const unsigned int*)nodes_raw;
        const unsigned char* mb = (const unsigned char*)masks_raw;
        int lane = threadIdx.x;
        unsigned int oddw = nw[2 * lane + 1];             // int64 LE hi words all 0
        unsigned char b0 = mb[lane], b1 = mb[32 + lane];  // int32-bool: k%4!=0 zero
        int nviol = (oddw != 0u);
        int mviol = (((lane & 3) != 0) && b0 != 0) |
                    ((((32 + lane) & 3) != 0) && b1 != 0);
        unsigned int vn = __ballot_sync(0xFFFFFFFFu, nviol);
        unsigned int vm = __ballot_sync(0xFFFFFFFFu, mviol);
        if (lane == 0) { s_n64 = (vn == 0u); s_m32 = (vm == 0u); }
    }
    __syncthreads();

    const int idx = blockIdx.x * BPREP + threadIdx.x;   // padded index
    if (idx < PTOT) {
        const int walk = idx >> 5;
        const int s    = idx & 31;
        const int half = s >> 4;
        const int k    = s & 15;

        if (k >= 10) {
            g_pnp[idx] = 32;                            // pad slots
        } else {
            const int i = walk * 20 + half * 10 + k;    // real flat position
            const unsigned int*  n32p = (const unsigned int*)nodes_raw;
            const unsigned char* mbp  = (const unsigned char*)masks_raw;
            const unsigned int*  m32p = (const unsigned int*)masks_raw;

            int  v = (int)(s_n64 ? n32p[i * 2] : n32p[i]) & 31;
            bool m = s_m32 ? (m32p[i] != 0u) : (mbp[i] != 0);
            g_pnp[idx] = m ? (unsigned char)v : (unsigned char)32;

            float t = times[i] * 0.2f;
            g_e2[i] = make_float2(__expf(t), __expf(-t));
        }
    }

    // PDL: make stores visible, then allow the dependent grid to launch.
    __threadfence();
    cudaTriggerProgrammaticLaunchCompletion();
}

__global__ __launch_bounds__(BDIM)
void cooc_kernel(float* __restrict__ out)
{
    const int r   = blockIdx.x;   // 0..63
    const int b   = blockIdx.y;   // 0..7
    const int tid = threadIdx.x;

    const int wA = r, wB = 127 - r;
    const int nA = 128 - r;       // row-A targets (w2 in [r,127]); nB = r+1

    __shared__ float        dvals[32];          // exp(-d^2/4), 0 for d>=20
    __shared__ unsigned int nmA[33], nmB[33];   // [32] stays 0 (sentinel)
    __shared__ float2       sA[32], sB[32];     // entries >=20 are (0,0)
    __shared__ float        acc[129];

    // ---- prep-independent prologue (overlaps with prep via PDL) ----
    if (tid < 32) {
        dvals[tid] = (tid < 20) ? __expf(-0.25f * (float)(tid * tid)) : 0.0f;
        sA[tid] = make_float2(0.0f, 0.0f);
        sB[tid] = make_float2(0.0f, 0.0f);
        nmA[tid] = 0u; nmB[tid] = 0u;
    }
    if (tid == 32) { nmA[32] = 0u; nmB[32] = 0u; }
    if (tid >= 64 && tid < 64 + 129) acc[tid - 64] = 0.0f;
    __syncthreads();

    // ---- wait for prep's writes before reading g_pnp / g_e2 ----
    cudaGridDependencySynchronize();

    if (tid < 20) {
        int l = tid;
        int pslot = (b * 128 + wA) * 32 + (l >= 10 ? 16 + (l - 10) : l);
        int v = g_pnp[pslot];
        sA[l] = g_e2[(b * 128 + wA) * 20 + l];
        if (v < 32) atomicOr(&nmA[v], 1u << l);
    } else if (tid >= 32 && tid < 52) {
        int l = tid - 32;
        int pslot = (b * 128 + wB) * 32 + (l >= 10 ? 16 + (l - 10) : l);
        int v = g_pnp[pslot];
        sB[l] = g_e2[(b * 128 + wB) * 20 + l];
        if (v < 32) atomicOr(&nmB[v], 1u << l);
    }
    __syncthreads();

    const int pair = tid >> 1;        // 0..143 (129 real targets)
    const int half = tid & 1;
    const bool active = (pair < 129);
    const bool rowA   = active ? (pair < nA) : true;
    int w2 = rowA ? (wA + (active ? pair : 0)) : (wB + (pair - nA));
    if (!active) w2 = 127;            // safe in-bounds addresses; result discarded

    const unsigned int* NM = rowA ? nmA : nmB;
    const float2*       S  = rowA ? sA  : sB;

    // prefetch: 10 node bytes (1 x LDG.128, padded layout) + 10 float2 (5 x LDG.128)
    const uint4 pn4 = *(const uint4*)&g_pnp[(b * 128 + w2) * 32 + half * 16];
    const float4* ep = (const float4*)(g_e2 + (b * 128 + w2) * 20 + half * 10);
    float4 e4[5];
#pragma unroll
    for (int q = 0; q < 5; q++) e4[q] = ep[q];
    const unsigned int pw[4] = { pn4.x, pn4.y, pn4.z, pn4.w };

    const int ljbase = half * 10;
    float a = 0.0f;
#pragma unroll
    for (int k = 0; k < 10; k++) {
        const float4 f = e4[k >> 1];
        const float ex = (k & 1) ? f.z : f.x;
        const float ey = (k & 1) ? f.w : f.y;
        const unsigned int vk = (pw[k >> 2] >> ((k & 3) * 8)) & 0xFFu;
        unsigned int bits = NM[vk];
        const int lj = ljbase + k;

        // two inline slots; empty slot -> li=-1 -> S[31]=(0,0) and dvals pad=0
        int li0 = __ffs(bits) - 1;
        unsigned int b1 = bits & (bits - 1);
        int li1 = __ffs(b1) - 1;
        unsigned int rest = b1 & (b1 - 1);
        {
            float2 sv = S[li0 & 31];
            int d = li0 - lj; d = d < 0 ? -d : d;
            a += dvals[d] * fminf(ex * sv.y, ey * sv.x);
        }
        {
            float2 sv = S[li1 & 31];
            int d = li1 - lj; d = d < 0 ? -d : d;
            a += dvals[d] * fminf(ex * sv.y, ey * sv.x);
        }
        if (rest) {                    // multiplicity >= 3: ~1.4% of positions
#pragma unroll 1
            do {
                int li = __ffs(rest) - 1;
                rest &= rest - 1;
                float2 sv = S[li];
                int d = li - lj; d = d < 0 ? -d : d;
                a += dvals[d] * fminf(ex * sv.y, ey * sv.x);
            } while (rest);
        }
    }

    // combine the two halves of each target (adjacent lanes), single plain store
    a += __shfl_xor_sync(0xFFFFFFFFu, a, 1);
    if (active && half == 0) acc[pair] = a;
    __syncthreads();

    if (tid < 129) {
        const bool rA = (tid < nA);
        const int  w1 = rA ? wA : wB;
        const int  wc = rA ? (wA + tid) : (wB + (tid - nA));
        float v = tanhf(fminf(acc[tid], 10.0f));   // acc >= 0
        out[(b * 128 + w1) * 128 + wc] = v;
        out[(b * 128 + wc) * 128 + w1] = v;
    }
}

extern "C" void kernel_launch(void* const* d_in, const int* in_sizes, int n_in,
                              void* d_out, int out_size)
{
    const void*  nodes = d_in[0];
    const void*  masks = d_in[1];
    const float* times = (const float*)d_in[2];
    float*       out   = (float*)d_out;

    prep_kernel<<<PTOT / BPREP, BPREP>>>(nodes, masks, times);

    // cooc with Programmatic Dependent Launch: may start while prep drains;
    // it synchronizes via cudaGridDependencySynchronize() before reading.
    cudaLaunchConfig_t cfg = {};
    cfg.gridDim  = dim3(64, 8, 1);
    cfg.blockDim = dim3(BDIM, 1, 1);
    cfg.dynamicSmemBytes = 0;
    cfg.stream = 0;
    cudaLaunchAttribute attrs[1];
    attrs[0].id = cudaLaunchAttributeProgrammaticStreamSerialization;
    attrs[0].val.programmaticStreamSerializationAllowed = 1;
    cfg.attrs = attrs;
    cfg.numAttrs = 1;
    cudaLaunchKernelEx(&cfg, cooc_kernel, out);
}

// round 11
// speedup vs baseline: 1.0130x; 1.0130x over previous
#include <cuda_runtime.h>
#include <cuda_bf16.h>
#include <cstdint>

// TemporalCooccurrenceMatrix — round 11: single fused kernel.
// No prep stage: each CTA dtype-detects (warp ballot, L2-resident), loads raw
// inputs, computes its own e^{+-t/5} (MUFU is cheap: ~20 warp-instrs/warp),
// then runs the proven predicated 2-slot pair loop. Direct epilogue (no acc
// smem / final barrier): half==0 thread tanh+stores both symmetric cells.
//
// C[b,w1,w2] = sum_{l1,l2} [node==][mask&mask] * e^{-(l1-l2)^2/4}*e^{-|t1-t2|/5}
// out = tanh(min(C,10)); symmetric -> rows r and 127-r paired per CTA (512 CTAs).
// e^{-|a-b|/5} = min(e^{a/5}e^{-b/5}, e^{-a/5}e^{b/5}).

#define BDIM 288              // 2 threads x 129 targets = 258 active

__global__ __launch_bounds__(BDIM)
void cooc_fused(const void* __restrict__ nodes_raw,
                const void* __restrict__ masks_raw,
                const float* __restrict__ times,
                float* __restrict__ out)
{
    const int r   = blockIdx.x;   // 0..63
    const int b   = blockIdx.y;   // 0..7
    const int tid = threadIdx.x;

    const int wA = r, wB = 127 - r;
    const int nA = 128 - r;       // row-A targets (w2 in [r,127]); nB = r+1

    __shared__ float        dvals[32];          // exp(-d^2/4), 0 for d>=20
    __shared__ unsigned int nmA[33], nmB[33];   // [32] stays 0 (sentinel)
    __shared__ float2       sA[32], sB[32];     // entries >=20 are (0,0)
    __shared__ int          s_n64, s_m32;

    // ---- target identity ----
    const int  pair   = tid >> 1;               // 0..143 (129 real)
    const int  half   = tid & 1;
    const bool active = (pair < 129);
    const bool rowA   = active ? (pair < nA) : true;
    int w2 = rowA ? (wA + (active ? pair : 0)) : (wB + (pair - nA));
    if (!active) w2 = 127;                      // safe addresses, result discarded
    const int jbase = (b * 128 + w2) * 20 + half * 10;

    // ---- phase A: detection-independent loads + table init (parallel) ----
    if (tid < 32) {                             // warp 0: dtype detection
        const unsigned int*  nw = (const unsigned int*)nodes_raw;
        const unsigned char* mb = (const unsigned char*)masks_raw;
        unsigned int oddw = nw[2 * tid + 1];             // int64 LE hi words all 0
        unsigned char b0 = mb[tid], b1 = mb[32 + tid];   // int32-bool: k%4!=0 zero
        int nviol = (oddw != 0u);
        int mviol = (((tid & 3) != 0) && b0 != 0) |
                    ((((32 + tid) & 3) != 0) && b1 != 0);
        unsigned int vn = __ballot_sync(0xFFFFFFFFu, nviol);
        unsigned int vm = __ballot_sync(0xFFFFFFFFu, mviol);
        if (tid == 0) { s_n64 = (vn == 0u); s_m32 = (vm == 0u); }
    }
    if (tid >= 64  && tid < 96)  dvals[tid - 64] =
        (tid - 64 < 20) ? __expf(-0.25f * (float)((tid - 64) * (tid - 64))) : 0.0f;
    if (tid >= 96  && tid < 129) nmA[tid - 96]  = 0u;
    if (tid >= 129 && tid < 162) nmB[tid - 129] = 0u;
    if (tid >= 162 && tid < 174) sA[20 + tid - 162] = make_float2(0.0f, 0.0f);
    if (tid >= 174 && tid < 186) sB[20 + tid - 174] = make_float2(0.0f, 0.0f);

    // target times: 10 floats, 8B-aligned -> 5 x LDG.64 (issued pre-barrier)
    float2 t2[5];
    {
        const float2* tp = (const float2*)(times + jbase);
#pragma unroll
        for (int q = 0; q < 5; q++) t2[q] = tp[q];
    }
    __syncthreads();

    const int n64 = s_n64, m32 = s_m32;
    const unsigned int*  n32p = (const unsigned int*)nodes_raw;
    const unsigned char* mbp  = (const unsigned char*)masks_raw;
    const unsigned int*  m32p = (const unsigned int*)masks_raw;

    // ---- phase B: node/mask loads + row tables + target exps ----
    // row build: threads 0..19 -> row A, 32..51 -> row B
    if (tid < 20) {
        const int i = (b * 128 + wA) * 20 + tid;
        int  v = (int)(n64 ? n32p[i * 2] : n32p[i]) & 31;
        bool m = m32 ? (m32p[i] != 0u) : (mbp[i] != 0);
        float t = times[i] * 0.2f;
        sA[tid] = make_float2(__expf(t), __expf(-t));
        if (m) atomicOr(&nmA[v], 1u << tid);
    } else if (tid >= 32 && tid < 52) {
        const int l = tid - 32;
        const int i = (b * 128 + wB) * 20 + l;
        int  v = (int)(n64 ? n32p[i * 2] : n32p[i]) & 31;
        bool m = m32 ? (m32p[i] != 0u) : (mbp[i] != 0);
        float t = times[i] * 0.2f;
        sB[l] = make_float2(__expf(t), __expf(-t));
        if (m) atomicOr(&nmB[v], 1u << l);
    }

    // target nodes+masks -> vk[10] in [0,32]
    int vk[10];
    if (n64) {
        const uint4* np = (const uint4*)((const char*)nodes_raw + (size_t)jbase * 8);
#pragma unroll
        for (int q = 0; q < 5; q++) {
            uint4 u = np[q];                     // two int64: low words .x, .z
            vk[2 * q]     = (int)(u.x & 31u);
            vk[2 * q + 1] = (int)(u.z & 31u);
        }
    } else {
        const uint2* np = (const uint2*)((const char*)nodes_raw + (size_t)jbase * 4);
#pragma unroll
        for (int q = 0; q < 5; q++) {
            uint2 u = np[q];
            vk[2 * q]     = (int)(u.x & 31u);
            vk[2 * q + 1] = (int)(u.y & 31u);
        }
    }
    if (m32) {
#pragma unroll
        for (int k = 0; k < 10; k++)
            if (m32p[jbase + k] == 0u) vk[k] = 32;
    } else {
#pragma unroll
        for (int k = 0; k < 10; k++)
            if (mbp[jbase + k] == 0)   vk[k] = 32;
    }

    // target exps (MUFU; overlaps row build above)
    float ex[10], ey[10];
#pragma unroll
    for (int q = 0; q < 5; q++) {
        float ta = t2[q].x * 0.2f, tb = t2[q].y * 0.2f;
        ex[2 * q]     = __expf(ta);  ey[2 * q]     = __expf(-ta);
        ex[2 * q + 1] = __expf(tb);  ey[2 * q + 1] = __expf(-tb);
    }
    __syncthreads();

    // ---- phase C: predicated 2-slot pair loop ----
    const unsigned int* NM = rowA ? nmA : nmB;
    const float2*       S  = rowA ? sA  : sB;
    const int ljbase = half * 10;

    float a = 0.0f;
#pragma unroll
    for (int k = 0; k < 10; k++) {
        unsigned int bits = NM[vk[k]];
        const float exk = ex[k], eyk = ey[k];
        const int lj = ljbase + k;

        int li0 = __ffs(bits) - 1;               // empty -> -1 -> S[31]=(0,0)
        unsigned int b1 = bits & (bits - 1);
        int li1 = __ffs(b1) - 1;
        unsigned int rest = b1 & (b1 - 1);
        {
            float2 sv = S[li0 & 31];
            int d = li0 - lj; d = d < 0 ? -d : d;
            a += dvals[d] * fminf(exk * sv.y, eyk * sv.x);
        }
        {
            float2 sv = S[li1 & 31];
            int d = li1 - lj; d = d < 0 ? -d : d;
            a += dvals[d] * fminf(exk * sv.y, eyk * sv.x);
        }
        if (rest) {                              // multiplicity >= 3: ~1.4%
#pragma unroll 1
            do {
                int li = __ffs(rest) - 1;
                rest &= rest - 1;
                float2 sv = S[li];
                int d = li - lj; d = d < 0 ? -d : d;
                a += dvals[d] * fminf(exk * sv.y, eyk * sv.x);
            } while (rest);
        }
    }

    // ---- direct epilogue: combine halves, tanh, symmetric store ----
    a += __shfl_xor_sync(0xFFFFFFFFu, a, 1);
    if (active && half == 0) {
        const int w1 = rowA ? wA : wB;
        float v = tanhf(fminf(a, 10.0f));        // a >= 0
        out[(b * 128 + w1) * 128 + w2] = v;
        out[(b * 128 + w2) * 128 + w1] = v;
    }
}

extern "C" void kernel_launch(void* const* d_in, const int* in_sizes, int n_in,
                              void* d_out, int out_size)
{
    const void*  nodes = d_in[0];
    const void*  masks = d_in[1];
    const float* times = (const float*)d_in[2];
    float*       out   = (float*)d_out;

    dim3 grid(64, 8);
    cooc_fused<<<grid, BDIM>>>(nodes, masks, times, out);
}

// round 12
// speedup vs baseline: 1.0457x; 1.0323x over previous
#include <cuda_runtime.h>
#include <cuda_bf16.h>
#include <cstdint>

// TemporalCooccurrenceMatrix — round 12: fused kernel, 4 threads per target.
// Grid-limited occupancy (39%) was the binding constraint: 2 threads/target
// gave only 147K threads. Now 4 threads/target (5 positions each), BDIM=576,
// __launch_bounds__(576,3) to keep 3 CTAs/SM resident (regs <= 37).
//
// C[b,w1,w2] = sum_{l1,l2} [node==][mask&mask] * e^{-(l1-l2)^2/4}*e^{-|t1-t2|/5}
// out = tanh(min(C,10)); symmetric -> rows r and 127-r paired per CTA (512 CTAs).
// e^{-|a-b|/5} = min(e^{a/5}e^{-b/5}, e^{-a/5}e^{b/5}).

#define BDIM 576              // 4 threads x 129 targets = 516 active

__global__ __launch_bounds__(BDIM, 3)
void cooc_fused(const void* __restrict__ nodes_raw,
                const void* __restrict__ masks_raw,
                const float* __restrict__ times,
                float* __restrict__ out)
{
    const int r   = blockIdx.x;   // 0..63
    const int b   = blockIdx.y;   // 0..7
    const int tid = threadIdx.x;

    const int wA = r, wB = 127 - r;
    const int nA = 128 - r;       // row-A targets (w2 in [r,127]); nB = r+1

    __shared__ float        dvals[32];          // exp(-d^2/4), 0 for d>=20
    __shared__ unsigned int nmA[33], nmB[33];   // [32] stays 0 (sentinel)
    __shared__ float2       sA[32], sB[32];     // entries >=20 are (0,0)
    __shared__ int          s_n64, s_m32;

    // ---- target identity: 4 threads per target, 5 positions each ----
    const int  pair    = tid >> 2;              // 0..143 (129 real)
    const int  quarter = tid & 3;
    const bool active  = (pair < 129);
    const bool rowA    = active ? (pair < nA) : true;
    int w2 = rowA ? (wA + (active ? pair : 0)) : (wB + (pair - nA));
    if (!active) w2 = 127;                      // safe addresses, result discarded
    const int jbase = (b * 128 + w2) * 20 + quarter * 5;

    // ---- phase A: detection + smem init + layout-independent prefetch ----
    if (tid < 32) {                             // warp 0: dtype detection
        const unsigned int*  nw = (const unsigned int*)nodes_raw;
        const unsigned char* mb = (const unsigned char*)masks_raw;
        unsigned int oddw = nw[2 * tid + 1];             // int64 LE hi words all 0
        unsigned char b0 = mb[tid], b1 = mb[32 + tid];   // int32-bool: k%4!=0 zero
        int nviol = (oddw != 0u);
        int mviol = (((tid & 3) != 0) && b0 != 0) |
                    ((((32 + tid) & 3) != 0) && b1 != 0);
        unsigned int vn = __ballot_sync(0xFFFFFFFFu, nviol);
        unsigned int vm = __ballot_sync(0xFFFFFFFFu, mviol);
        if (tid == 0) { s_n64 = (vn == 0u); s_m32 = (vm == 0u); }
    }
    if (tid >= 64  && tid < 96)  dvals[tid - 64] =
        (tid - 64 < 20) ? __expf(-0.25f * (float)((tid - 64) * (tid - 64))) : 0.0f;
    if (tid >= 96  && tid < 129) nmA[tid - 96]  = 0u;
    if (tid >= 129 && tid < 162) nmB[tid - 129] = 0u;
    if (tid >= 162 && tid < 174) sA[20 + tid - 162] = make_float2(0.0f, 0.0f);
    if (tid >= 174 && tid < 186) sB[20 + tid - 174] = make_float2(0.0f, 0.0f);

    // target times: 5 scalar floats (independent -> MLP), issued pre-barrier
    float tv[5];
#pragma unroll
    for (int k = 0; k < 5; k++) tv[k] = times[jbase + k];
    __syncthreads();

    const int n64 = s_n64, m32 = s_m32;
    const unsigned int*  n32p = (const unsigned int*)nodes_raw;
    const unsigned char* mbp  = (const unsigned char*)masks_raw;
    const unsigned int*  m32p = (const unsigned int*)masks_raw;

    // ---- phase B: row tables + target node/mask loads + target exps ----
    if (tid < 20) {
        const int i = (b * 128 + wA) * 20 + tid;
        int  v = (int)(n64 ? n32p[i * 2] : n32p[i]) & 31;
        bool m = m32 ? (m32p[i] != 0u) : (mbp[i] != 0);
        float t = times[i] * 0.2f;
        sA[tid] = make_float2(__expf(t), __expf(-t));
        if (m) atomicOr(&nmA[v], 1u << tid);
    } else if (tid >= 32 && tid < 52) {
        const int l = tid - 32;
        const int i = (b * 128 + wB) * 20 + l;
        int  v = (int)(n64 ? n32p[i * 2] : n32p[i]) & 31;
        bool m = m32 ? (m32p[i] != 0u) : (mbp[i] != 0);
        float t = times[i] * 0.2f;
        sB[l] = make_float2(__expf(t), __expf(-t));
        if (m) atomicOr(&nmB[v], 1u << l);
    }

    // target nodes (5 scalar low-word loads) + masks -> vk[5] in [0,32]
    int vk[5];
    if (n64) {
#pragma unroll
        for (int k = 0; k < 5; k++) vk[k] = (int)(n32p[(jbase + k) * 2] & 31u);
    } else {
#pragma unroll
        for (int k = 0; k < 5; k++) vk[k] = (int)(n32p[jbase + k] & 31u);
    }
    if (m32) {
#pragma unroll
        for (int k = 0; k < 5; k++) if (m32p[jbase + k] == 0u) vk[k] = 32;
    } else {
#pragma unroll
        for (int k = 0; k < 5; k++) if (mbp[jbase + k] == 0)   vk[k] = 32;
    }

    // target exps (MUFU; overlaps row build)
    float ex[5], ey[5];
#pragma unroll
    for (int k = 0; k < 5; k++) {
        float t = tv[k] * 0.2f;
        ex[k] = __expf(t);
        ey[k] = __expf(-t);
    }
    __syncthreads();

    // ---- phase C: predicated 2-slot pair loop (5 positions) ----
    const unsigned int* NM = rowA ? nmA : nmB;
    const float2*       S  = rowA ? sA  : sB;
    const int ljbase = quarter * 5;

    float a0 = 0.0f, a1 = 0.0f;
#pragma unroll
    for (int k = 0; k < 5; k++) {
        unsigned int bits = NM[vk[k]];
        const float exk = ex[k], eyk = ey[k];
        const int lj = ljbase + k;

        int li0 = __ffs(bits) - 1;               // empty -> -1 -> S[31]=(0,0)
        unsigned int b1m = bits & (bits - 1);
        int li1 = __ffs(b1m) - 1;
        unsigned int rest = b1m & (b1m - 1);
        {
            float2 sv = S[li0 & 31];
            int d = li0 - lj; d = d < 0 ? -d : d;
            a0 += dvals[d] * fminf(exk * sv.y, eyk * sv.x);
        }
        {
            float2 sv = S[li1 & 31];
            int d = li1 - lj; d = d < 0 ? -d : d;
            a1 += dvals[d] * fminf(exk * sv.y, eyk * sv.x);
        }
        if (rest) {                              // multiplicity >= 3: ~1.4%
#pragma unroll 1
            do {
                int li = __ffs(rest) - 1;
                rest &= rest - 1;
                float2 sv = S[li];
                int d = li - lj; d = d < 0 ? -d : d;
                a0 += dvals[d] * fminf(exk * sv.y, eyk * sv.x);
            } while (rest);
        }
    }

    // ---- combine 4 lanes per target, tanh, symmetric store ----
    float a = a0 + a1;
    a += __shfl_xor_sync(0xFFFFFFFFu, a, 1);
    a += __shfl_xor_sync(0xFFFFFFFFu, a, 2);
    if (active && quarter == 0) {
        const int w1 = rowA ? wA : wB;
        float v = tanhf(fminf(a, 10.0f));        // a >= 0
        out[(b * 128 + w1) * 128 + w2] = v;
        out[(b * 128 + w2) * 128 + w1] = v;
    }
}

extern "C" void kernel_launch(void* const* d_in, const int* in_sizes, int n_in,
                              void* d_out, int out_size)
{
    const void*  nodes = d_in[0];
    const void*  masks = d_in[1];
    const float* times = (const float*)d_in[2];
    float*       out   = (float*)d_out;

    dim3 grid(64, 8);
    cooc_fused<<<grid, BDIM>>>(nodes, masks, times, out);
}